// round 1
// baseline (speedup 1.0000x reference)
#include <cuda_runtime.h>

// Problem constants (fixed shapes from reference)
#define BZ   16
#define CC   32
#define HH   384
#define WW   384
#define NKRN 32
#define HID  128
#define KOUT (NKRN * 9)          // 288
#define PLANE (HH * WW)          // 147456
#define NCH  (BZ * NKRN)         // 512 planes

// Scratch (allocation-free rule -> __device__ globals)
__device__ float g_pooled[BZ * CC];      // 512
__device__ float g_kernels[BZ * KOUT];   // 4608

// ---------------------------------------------------------------------------
// Kernel 1: global average pool per (b,c) plane.  512 blocks x 256 threads.
// ---------------------------------------------------------------------------
__global__ void pool_kernel(const float* __restrict__ x) {
    const int ch = blockIdx.x;                                  // b*C + c
    const float4* __restrict__ p =
        reinterpret_cast<const float4*>(x + (size_t)ch * PLANE);
    const int n4 = PLANE / 4;                                   // 36864

    float4 acc = make_float4(0.f, 0.f, 0.f, 0.f);
    for (int i = threadIdx.x; i < n4; i += blockDim.x) {
        float4 v = p[i];
        acc.x += v.x; acc.y += v.y; acc.z += v.z; acc.w += v.w;
    }
    float s = (acc.x + acc.y) + (acc.z + acc.w);
    #pragma unroll
    for (int o = 16; o; o >>= 1) s += __shfl_xor_sync(0xffffffffu, s, o);

    __shared__ float ws[8];
    const int wid = threadIdx.x >> 5, lid = threadIdx.x & 31;
    if (lid == 0) ws[wid] = s;
    __syncthreads();
    if (threadIdx.x == 0) {
        float t = 0.f;
        #pragma unroll
        for (int i = 0; i < 8; i++) t += ws[i];
        g_pooled[ch] = t * (1.0f / PLANE);
    }
}

// ---------------------------------------------------------------------------
// Kernel 2: tiny MLP, one block per batch sample.  16 blocks x 288 threads.
//   hidden = relu(pooled @ w1 + b1);  kernels = hidden @ w2 + b2
// ---------------------------------------------------------------------------
__global__ void mlp_kernel(const float* __restrict__ w1,
                           const float* __restrict__ b1,
                           const float* __restrict__ w2,
                           const float* __restrict__ b2) {
    const int b = blockIdx.x;
    const int t = threadIdx.x;
    __shared__ float sp[CC];
    __shared__ float sh[HID];

    if (t < CC) sp[t] = g_pooled[b * CC + t];
    __syncthreads();

    if (t < HID) {
        float a = b1[t];
        #pragma unroll
        for (int c = 0; c < CC; c++) a = fmaf(sp[c], w1[c * HID + t], a);
        sh[t] = fmaxf(a, 0.f);
    }
    __syncthreads();

    if (t < KOUT) {
        float a = b2[t];
        #pragma unroll 8
        for (int h = 0; h < HID; h++) a = fmaf(sh[h], w2[h * KOUT + t], a);
        g_kernels[b * KOUT + t] = a;
    }
}

// ---------------------------------------------------------------------------
// Kernel 3: per-plane dynamic depthwise 3x3 conv (zero padding).
// Tile: 128 cols x 32 rows per block, 256 threads.
// smem holds 34 rows x 136 floats (float4-aligned halo: smem col 0 == tile
// col -4).  Every smem access is a conflict-free LDS.128.  Each thread owns a
// 4x4 output patch with a 3-row register sliding window.
// ---------------------------------------------------------------------------
__global__ __launch_bounds__(256, 2)
void conv_kernel(const float* __restrict__ x, float* __restrict__ out) {
    __shared__ float smem[34][136];

    const int ch = blockIdx.z;                       // b*NK + k plane
    const float* __restrict__ xin = x + (size_t)ch * PLANE;
    float*       __restrict__ op  = out + (size_t)ch * PLANE;

    const int gx0 = blockIdx.x * 32 - 1;             // float4-col base (halo)
    const int gy0 = blockIdx.y * 32 - 1;             // row base (halo)

    // ---- fill smem tile (zero outside image) ----
    for (int i = threadIdx.x; i < 34 * 34; i += 256) {
        const int r  = i / 34;
        const int fc = i - r * 34;
        const int gy = gy0 + r;
        const int g4 = gx0 + fc;                     // float4 column index
        float4 v = make_float4(0.f, 0.f, 0.f, 0.f);
        if ((unsigned)gy < (unsigned)HH && (unsigned)g4 < (unsigned)(WW / 4))
            v = *reinterpret_cast<const float4*>(xin + (size_t)gy * WW + g4 * 4);
        *reinterpret_cast<float4*>(&smem[r][fc * 4]) = v;
    }

    // ---- per-plane 3x3 weights (uniform across block) ----
    float wk[9];
    #pragma unroll
    for (int i = 0; i < 9; i++) wk[i] = __ldg(&g_kernels[ch * 9 + i]);

    __syncthreads();

    const int j  = threadIdx.x & 31;                 // float4 output column
    const int tr = threadIdx.x >> 5;                 // thread-row 0..7
    const int cb = j * 4;                            // smem float col base
    const int sr0 = tr * 4;                          // first smem row of window

    float rows[3][12];

    #define LOADROW(SR, DST)                                               \
        do {                                                               \
            float4 _a = *reinterpret_cast<const float4*>(&smem[SR][cb]);   \
            float4 _b = *reinterpret_cast<const float4*>(&smem[SR][cb+4]); \
            float4 _c = *reinterpret_cast<const float4*>(&smem[SR][cb+8]); \
            (DST)[0]=_a.x; (DST)[1]=_a.y; (DST)[2]=_a.z; (DST)[3]=_a.w;    \
            (DST)[4]=_b.x; (DST)[5]=_b.y; (DST)[6]=_b.z; (DST)[7]=_b.w;    \
            (DST)[8]=_c.x; (DST)[9]=_c.y; (DST)[10]=_c.z; (DST)[11]=_c.w;  \
        } while (0)

    LOADROW(sr0 + 0, rows[0]);
    LOADROW(sr0 + 1, rows[1]);

    const int orow0 = blockIdx.y * 32 + tr * 4;      // first global output row
    const int ocol  = blockIdx.x * 128 + cb;         // global output col

    #pragma unroll
    for (int rr = 0; rr < 4; rr++) {
        LOADROW(sr0 + 2 + rr, rows[(rr + 2) % 3]);
        const float* ra = rows[rr % 3];              // input row orow-1
        const float* rb = rows[(rr + 1) % 3];        // input row orow
        const float* rc = rows[(rr + 2) % 3];        // input row orow+1

        float o[4];
        #pragma unroll
        for (int k = 0; k < 4; k++) {
            float a;
            a = wk[0] * ra[k + 3];
            a = fmaf(wk[1], ra[k + 4], a);
            a = fmaf(wk[2], ra[k + 5], a);
            a = fmaf(wk[3], rb[k + 3], a);
            a = fmaf(wk[4], rb[k + 4], a);
            a = fmaf(wk[5], rb[k + 5], a);
            a = fmaf(wk[6], rc[k + 3], a);
            a = fmaf(wk[7], rc[k + 4], a);
            a = fmaf(wk[8], rc[k + 5], a);
            o[k] = a;
        }
        *reinterpret_cast<float4*>(op + (size_t)(orow0 + rr) * WW + ocol) =
            make_float4(o[0], o[1], o[2], o[3]);
    }
    #undef LOADROW
}

// ---------------------------------------------------------------------------
extern "C" void kernel_launch(void* const* d_in, const int* in_sizes, int n_in,
                              void* d_out, int out_size) {
    const float* x  = (const float*)d_in[0];
    const float* w1 = (const float*)d_in[1];
    const float* b1 = (const float*)d_in[2];
    const float* w2 = (const float*)d_in[3];
    const float* b2 = (const float*)d_in[4];
    float* out = (float*)d_out;

    pool_kernel<<<NCH, 256>>>(x);
    mlp_kernel<<<BZ, 288>>>(w1, b1, w2, b2);

    dim3 grid(WW / 128, HH / 32, NCH);               // 3 x 12 x 512
    conv_kernel<<<grid, 256>>>(x, out);
}

// round 2
// speedup vs baseline: 1.0095x; 1.0095x over previous
#include <cuda_runtime.h>

// Problem constants (fixed shapes from reference)
#define BZ   16
#define CC   32
#define HH   384
#define WW   384
#define NKRN 32
#define HID  128
#define KOUT (NKRN * 9)          // 288
#define PLANE (HH * WW)          // 147456
#define NCH  (BZ * NKRN)         // 512 planes

// Scratch (allocation-free rule -> __device__ globals)
__device__ float g_pooled[BZ * CC];      // 512
__device__ float g_kernels[BZ * KOUT];   // 4608

// ---------------------------------------------------------------------------
// Kernel 1: global average pool per (b,c) plane.  512 blocks x 256 threads.
// ---------------------------------------------------------------------------
__global__ void pool_kernel(const float* __restrict__ x) {
    const int ch = blockIdx.x;                                  // b*C + c
    const float4* __restrict__ p =
        reinterpret_cast<const float4*>(x + (size_t)ch * PLANE);
    const int n4 = PLANE / 4;                                   // 36864

    float4 acc = make_float4(0.f, 0.f, 0.f, 0.f);
    for (int i = threadIdx.x; i < n4; i += blockDim.x) {
        float4 v = p[i];
        acc.x += v.x; acc.y += v.y; acc.z += v.z; acc.w += v.w;
    }
    float s = (acc.x + acc.y) + (acc.z + acc.w);
    #pragma unroll
    for (int o = 16; o; o >>= 1) s += __shfl_xor_sync(0xffffffffu, s, o);

    __shared__ float ws[8];
    const int wid = threadIdx.x >> 5, lid = threadIdx.x & 31;
    if (lid == 0) ws[wid] = s;
    __syncthreads();
    if (threadIdx.x == 0) {
        float t = 0.f;
        #pragma unroll
        for (int i = 0; i < 8; i++) t += ws[i];
        g_pooled[ch] = t * (1.0f / PLANE);
    }
}

// ---------------------------------------------------------------------------
// Kernel 2: tiny MLP, one block per batch sample.  16 blocks x 288 threads.
//   hidden = relu(pooled @ w1 + b1);  kernels = hidden @ w2 + b2
// ---------------------------------------------------------------------------
__global__ void mlp_kernel(const float* __restrict__ w1,
                           const float* __restrict__ b1,
                           const float* __restrict__ w2,
                           const float* __restrict__ b2) {
    const int b = blockIdx.x;
    const int t = threadIdx.x;
    __shared__ float sp[CC];
    __shared__ float sh[HID];

    if (t < CC) sp[t] = g_pooled[b * CC + t];
    __syncthreads();

    if (t < HID) {
        float a = b1[t];
        #pragma unroll
        for (int c = 0; c < CC; c++) a = fmaf(sp[c], w1[c * HID + t], a);
        sh[t] = fmaxf(a, 0.f);
    }
    __syncthreads();

    if (t < KOUT) {
        float a = b2[t];
        #pragma unroll 8
        for (int h = 0; h < HID; h++) a = fmaf(sh[h], w2[h * KOUT + t], a);
        g_kernels[b * KOUT + t] = a;
    }
}

// ---------------------------------------------------------------------------
// Kernel 3: per-plane dynamic depthwise 3x3 conv (zero padding).
// Tile: 128 cols x 32 rows per block, 256 threads.
// smem holds 34 rows x 136 floats (float4-aligned halo: smem col 0 == tile
// col -4).  Every smem access is a conflict-free LDS.128.  Each thread owns a
// 4x4 output patch with a 3-row register sliding window.
// ---------------------------------------------------------------------------
__global__ __launch_bounds__(256, 2)
void conv_kernel(const float* __restrict__ x, float* __restrict__ out) {
    __shared__ float smem[34][136];

    const int ch = blockIdx.z;                       // b*NK + k plane
    const float* __restrict__ xin = x + (size_t)ch * PLANE;
    float*       __restrict__ op  = out + (size_t)ch * PLANE;

    const int gx0 = blockIdx.x * 32 - 1;             // float4-col base (halo)
    const int gy0 = blockIdx.y * 32 - 1;             // row base (halo)

    // ---- fill smem tile (zero outside image) ----
    for (int i = threadIdx.x; i < 34 * 34; i += 256) {
        const int r  = i / 34;
        const int fc = i - r * 34;
        const int gy = gy0 + r;
        const int g4 = gx0 + fc;                     // float4 column index
        float4 v = make_float4(0.f, 0.f, 0.f, 0.f);
        if ((unsigned)gy < (unsigned)HH && (unsigned)g4 < (unsigned)(WW / 4))
            v = *reinterpret_cast<const float4*>(xin + (size_t)gy * WW + g4 * 4);
        *reinterpret_cast<float4*>(&smem[r][fc * 4]) = v;
    }

    // ---- per-plane 3x3 weights (uniform across block) ----
    float wk[9];
    #pragma unroll
    for (int i = 0; i < 9; i++) wk[i] = __ldg(&g_kernels[ch * 9 + i]);

    __syncthreads();

    const int j  = threadIdx.x & 31;                 // float4 output column
    const int tr = threadIdx.x >> 5;                 // thread-row 0..7
    const int cb = j * 4;                            // smem float col base
    const int sr0 = tr * 4;                          // first smem row of window

    float rows[3][12];

    #define LOADROW(SR, DST)                                               \
        do {                                                               \
            float4 _a = *reinterpret_cast<const float4*>(&smem[SR][cb]);   \
            float4 _b = *reinterpret_cast<const float4*>(&smem[SR][cb+4]); \
            float4 _c = *reinterpret_cast<const float4*>(&smem[SR][cb+8]); \
            (DST)[0]=_a.x; (DST)[1]=_a.y; (DST)[2]=_a.z; (DST)[3]=_a.w;    \
            (DST)[4]=_b.x; (DST)[5]=_b.y; (DST)[6]=_b.z; (DST)[7]=_b.w;    \
            (DST)[8]=_c.x; (DST)[9]=_c.y; (DST)[10]=_c.z; (DST)[11]=_c.w;  \
        } while (0)

    LOADROW(sr0 + 0, rows[0]);
    LOADROW(sr0 + 1, rows[1]);

    const int orow0 = blockIdx.y * 32 + tr * 4;      // first global output row
    const int ocol  = blockIdx.x * 128 + cb;         // global output col

    #pragma unroll
    for (int rr = 0; rr < 4; rr++) {
        LOADROW(sr0 + 2 + rr, rows[(rr + 2) % 3]);
        const float* ra = rows[rr % 3];              // input row orow-1
        const float* rb = rows[(rr + 1) % 3];        // input row orow
        const float* rc = rows[(rr + 2) % 3];        // input row orow+1

        float o[4];
        #pragma unroll
        for (int k = 0; k < 4; k++) {
            float a;
            a = wk[0] * ra[k + 3];
            a = fmaf(wk[1], ra[k + 4], a);
            a = fmaf(wk[2], ra[k + 5], a);
            a = fmaf(wk[3], rb[k + 3], a);
            a = fmaf(wk[4], rb[k + 4], a);
            a = fmaf(wk[5], rb[k + 5], a);
            a = fmaf(wk[6], rc[k + 3], a);
            a = fmaf(wk[7], rc[k + 4], a);
            a = fmaf(wk[8], rc[k + 5], a);
            o[k] = a;
        }
        *reinterpret_cast<float4*>(op + (size_t)(orow0 + rr) * WW + ocol) =
            make_float4(o[0], o[1], o[2], o[3]);
    }
    #undef LOADROW
}

// ---------------------------------------------------------------------------
extern "C" void kernel_launch(void* const* d_in, const int* in_sizes, int n_in,
                              void* d_out, int out_size) {
    const float* x  = (const float*)d_in[0];
    const float* w1 = (const float*)d_in[1];
    const float* b1 = (const float*)d_in[2];
    const float* w2 = (const float*)d_in[3];
    const float* b2 = (const float*)d_in[4];
    float* out = (float*)d_out;

    pool_kernel<<<NCH, 256>>>(x);
    mlp_kernel<<<BZ, 288>>>(w1, b1, w2, b2);

    dim3 grid(WW / 128, HH / 32, NCH);               // 3 x 12 x 512
    conv_kernel<<<grid, 256>>>(x, out);
}

// round 3
// speedup vs baseline: 1.0096x; 1.0002x over previous
#include <cuda_runtime.h>

// Problem constants (fixed shapes from reference)
#define BZ   16
#define CC   32
#define HH   384
#define WW   384
#define NKRN 32
#define HID  128
#define KOUT (NKRN * 9)          // 288
#define PLANE (HH * WW)          // 147456
#define NCH  (BZ * NKRN)         // 512 planes

// Scratch (allocation-free rule -> __device__ globals)
__device__ float g_pooled[BZ * CC];      // 512
__device__ float g_kernels[BZ * KOUT];   // 4608

// ---------------------------------------------------------------------------
// Kernel 1: global average pool per (b,c) plane.  512 blocks x 256 threads.
// ---------------------------------------------------------------------------
__global__ void pool_kernel(const float* __restrict__ x) {
    const int ch = blockIdx.x;                                  // b*C + c
    const float4* __restrict__ p =
        reinterpret_cast<const float4*>(x + (size_t)ch * PLANE);
    const int n4 = PLANE / 4;                                   // 36864

    float4 acc = make_float4(0.f, 0.f, 0.f, 0.f);
    for (int i = threadIdx.x; i < n4; i += blockDim.x) {
        float4 v = p[i];
        acc.x += v.x; acc.y += v.y; acc.z += v.z; acc.w += v.w;
    }
    float s = (acc.x + acc.y) + (acc.z + acc.w);
    #pragma unroll
    for (int o = 16; o; o >>= 1) s += __shfl_xor_sync(0xffffffffu, s, o);

    __shared__ float ws[8];
    const int wid = threadIdx.x >> 5, lid = threadIdx.x & 31;
    if (lid == 0) ws[wid] = s;
    __syncthreads();
    if (threadIdx.x == 0) {
        float t = 0.f;
        #pragma unroll
        for (int i = 0; i < 8; i++) t += ws[i];
        g_pooled[ch] = t * (1.0f / PLANE);
    }
}

// ---------------------------------------------------------------------------
// Kernel 2: tiny MLP, one block per batch sample.  16 blocks x 288 threads.
//   hidden = relu(pooled @ w1 + b1);  kernels = hidden @ w2 + b2
// ---------------------------------------------------------------------------
__global__ void mlp_kernel(const float* __restrict__ w1,
                           const float* __restrict__ b1,
                           const float* __restrict__ w2,
                           const float* __restrict__ b2) {
    const int b = blockIdx.x;
    const int t = threadIdx.x;
    __shared__ float sp[CC];
    __shared__ float sh[HID];

    if (t < CC) sp[t] = g_pooled[b * CC + t];
    __syncthreads();

    if (t < HID) {
        float a = b1[t];
        #pragma unroll
        for (int c = 0; c < CC; c++) a = fmaf(sp[c], w1[c * HID + t], a);
        sh[t] = fmaxf(a, 0.f);
    }
    __syncthreads();

    if (t < KOUT) {
        float a = b2[t];
        #pragma unroll 8
        for (int h = 0; h < HID; h++) a = fmaf(sh[h], w2[h * KOUT + t], a);
        g_kernels[b * KOUT + t] = a;
    }
}

// ---------------------------------------------------------------------------
// Kernel 3: per-plane dynamic depthwise 3x3 conv (zero padding).
// Tile: 128 cols x 32 rows per block, 256 threads.
// smem holds 34 rows x 136 floats (float4-aligned halo: smem col 0 == tile
// col -4).  Every smem access is a conflict-free LDS.128.  Each thread owns a
// 4x4 output patch with a 3-row register sliding window.
// ---------------------------------------------------------------------------
__global__ __launch_bounds__(256, 2)
void conv_kernel(const float* __restrict__ x, float* __restrict__ out) {
    __shared__ float smem[34][136];

    const int ch = blockIdx.z;                       // b*NK + k plane
    const float* __restrict__ xin = x + (size_t)ch * PLANE;
    float*       __restrict__ op  = out + (size_t)ch * PLANE;

    const int gx0 = blockIdx.x * 32 - 1;             // float4-col base (halo)
    const int gy0 = blockIdx.y * 32 - 1;             // row base (halo)

    // ---- fill smem tile (zero outside image) ----
    for (int i = threadIdx.x; i < 34 * 34; i += 256) {
        const int r  = i / 34;
        const int fc = i - r * 34;
        const int gy = gy0 + r;
        const int g4 = gx0 + fc;                     // float4 column index
        float4 v = make_float4(0.f, 0.f, 0.f, 0.f);
        if ((unsigned)gy < (unsigned)HH && (unsigned)g4 < (unsigned)(WW / 4))
            v = *reinterpret_cast<const float4*>(xin + (size_t)gy * WW + g4 * 4);
        *reinterpret_cast<float4*>(&smem[r][fc * 4]) = v;
    }

    // ---- per-plane 3x3 weights (uniform across block) ----
    float wk[9];
    #pragma unroll
    for (int i = 0; i < 9; i++) wk[i] = __ldg(&g_kernels[ch * 9 + i]);

    __syncthreads();

    const int j  = threadIdx.x & 31;                 // float4 output column
    const int tr = threadIdx.x >> 5;                 // thread-row 0..7
    const int cb = j * 4;                            // smem float col base
    const int sr0 = tr * 4;                          // first smem row of window

    float rows[3][12];

    #define LOADROW(SR, DST)                                               \
        do {                                                               \
            float4 _a = *reinterpret_cast<const float4*>(&smem[SR][cb]);   \
            float4 _b = *reinterpret_cast<const float4*>(&smem[SR][cb+4]); \
            float4 _c = *reinterpret_cast<const float4*>(&smem[SR][cb+8]); \
            (DST)[0]=_a.x; (DST)[1]=_a.y; (DST)[2]=_a.z; (DST)[3]=_a.w;    \
            (DST)[4]=_b.x; (DST)[5]=_b.y; (DST)[6]=_b.z; (DST)[7]=_b.w;    \
            (DST)[8]=_c.x; (DST)[9]=_c.y; (DST)[10]=_c.z; (DST)[11]=_c.w;  \
        } while (0)

    LOADROW(sr0 + 0, rows[0]);
    LOADROW(sr0 + 1, rows[1]);

    const int orow0 = blockIdx.y * 32 + tr * 4;      // first global output row
    const int ocol  = blockIdx.x * 128 + cb;         // global output col

    #pragma unroll
    for (int rr = 0; rr < 4; rr++) {
        LOADROW(sr0 + 2 + rr, rows[(rr + 2) % 3]);
        const float* ra = rows[rr % 3];              // input row orow-1
        const float* rb = rows[(rr + 1) % 3];        // input row orow
        const float* rc = rows[(rr + 2) % 3];        // input row orow+1

        float o[4];
        #pragma unroll
        for (int k = 0; k < 4; k++) {
            float a;
            a = wk[0] * ra[k + 3];
            a = fmaf(wk[1], ra[k + 4], a);
            a = fmaf(wk[2], ra[k + 5], a);
            a = fmaf(wk[3], rb[k + 3], a);
            a = fmaf(wk[4], rb[k + 4], a);
            a = fmaf(wk[5], rb[k + 5], a);
            a = fmaf(wk[6], rc[k + 3], a);
            a = fmaf(wk[7], rc[k + 4], a);
            a = fmaf(wk[8], rc[k + 5], a);
            o[k] = a;
        }
        *reinterpret_cast<float4*>(op + (size_t)(orow0 + rr) * WW + ocol) =
            make_float4(o[0], o[1], o[2], o[3]);
    }
    #undef LOADROW
}

// ---------------------------------------------------------------------------
extern "C" void kernel_launch(void* const* d_in, const int* in_sizes, int n_in,
                              void* d_out, int out_size) {
    const float* x  = (const float*)d_in[0];
    const float* w1 = (const float*)d_in[1];
    const float* b1 = (const float*)d_in[2];
    const float* w2 = (const float*)d_in[3];
    const float* b2 = (const float*)d_in[4];
    float* out = (float*)d_out;

    pool_kernel<<<NCH, 256>>>(x);
    mlp_kernel<<<BZ, 288>>>(w1, b1, w2, b2);

    dim3 grid(WW / 128, HH / 32, NCH);               // 3 x 12 x 512
    conv_kernel<<<grid, 256>>>(x, out);
}